// round 11
// baseline (speedup 1.0000x reference)
#include <cuda_runtime.h>
#include <cstdint>

#define BATCH 256
#define SEQ   197
#define DIMC  768
#define HEADS 12
#define HD    64
#define NRD   732
#define MTOT  (BATCH*SEQ)      /* 50432 */
#define QSCALE 0.125f          /* 64^-0.5 */

// ---------------- scratch (static device globals; no allocation) ----------------
__device__ __align__(16) float g_Q[BATCH*HEADS*SEQ*HD];
__device__ __align__(16) float g_K[BATCH*HEADS*SEQ*HD];
__device__ __align__(16) float g_V[BATCH*HEADS*SEQ*HD];
__device__ __align__(16) float g_ATT[(size_t)MTOT*DIMC];
__device__ __align__(16) float g_BIAS[HEADS*SEQ*SEQ];

// ---------------- helpers ----------------
__device__ __forceinline__ float to_tf32(float x){
    float r; asm("cvt.rna.tf32.f32 %0, %1;" : "=f"(r) : "f"(x)); return r;
}
__device__ __forceinline__ void cp16(void* s, const void* g){
    unsigned saddr = (unsigned)__cvta_generic_to_shared(s);
    asm volatile("cp.async.cg.shared.global [%0], [%1], 16;\n" :: "r"(saddr), "l"(g));
}
__device__ __forceinline__ void mma8(float* c, const uint32_t* a, const uint32_t* b){
    asm volatile("mma.sync.aligned.m16n8k8.row.col.f32.tf32.tf32.f32 "
        "{%0,%1,%2,%3}, {%4,%5,%6,%7}, {%8,%9}, {%0,%1,%2,%3};"
        : "+f"(c[0]),"+f"(c[1]),"+f"(c[2]),"+f"(c[3])
        : "r"(a[0]),"r"(a[1]),"r"(a[2]),"r"(a[3]),"r"(b[0]),"r"(b[1]));
}
__device__ __forceinline__ uint32_t fbits(float x){ return __float_as_uint(x); }

// ---------------- bias gather: g_BIAS[h][i][j] = table[rel_index[i][j]][h] ----------------
__global__ void bias_gather_kernel(const float* __restrict__ table,
                                   const int* __restrict__ rel_index){
    int idx = blockIdx.x * 256 + threadIdx.x;
    const int tot = HEADS*SEQ*SEQ;
    if (idx >= tot) return;
    int h  = idx / (SEQ*SEQ);
    int ij = idx - h*(SEQ*SEQ);
    g_BIAS[idx] = table[rel_index[ij]*HEADS + h];
}

// ---------------- TF32 GEMM 128x128x32, C[m,n] = sum_k A[m,k]*W[n,k] ----------------
// MODE 0: A = x param, epilogue -> Q (scale+q_bias), K, V  (n spans 2304)
// MODE 1: A = g_ATT,   epilogue -> out + proj_b            (n spans 768)
#define SMA 36              /* smem row stride (floats), padded vs 32 */
#define TBUF 4608           /* 128*36 floats per buffer */
template<int MODE>
__global__ void __launch_bounds__(256,2) gemm_tf32(
    const float* __restrict__ A, const float* __restrict__ W,
    const float* __restrict__ bias_a, const float* __restrict__ bias_b,
    float* __restrict__ Out)
{
    const int K = DIMC;
    extern __shared__ float sm[];
    float* As = sm;             // 2 * TBUF
    float* Bs = sm + 2*TBUF;    // 2 * TBUF
    const int tid = threadIdx.x;
    const int m0 = blockIdx.y * 128;
    const int n0 = blockIdx.x * 128;
    const float* Ap = (MODE == 0) ? A : g_ATT;

    float acc[2][8][4];
    #pragma unroll
    for (int i=0;i<2;i++)
        #pragma unroll
        for (int j=0;j<8;j++)
            #pragma unroll
            for (int r=0;r<4;r++) acc[i][j][r]=0.f;

    const int NT = K/32;  // 24
    auto load_tile = [&](int kt, int buf){
        const int k0 = kt*32;
        #pragma unroll
        for (int i=0;i<4;i++){
            int idx = tid + i*256;               // 0..1023
            int row = idx >> 3, c4 = (idx & 7)*4;
            cp16(&As[buf*TBUF + row*SMA + c4], &Ap[(size_t)(m0+row)*K + k0 + c4]);
        }
        #pragma unroll
        for (int i=0;i<4;i++){
            int idx = tid + i*256;
            int row = idx >> 3, c4 = (idx & 7)*4;
            cp16(&Bs[buf*TBUF + row*SMA + c4], &W[(size_t)(n0+row)*K + k0 + c4]);
        }
        asm volatile("cp.async.commit_group;");
    };
    load_tile(0, 0);

    const int wid = tid>>5, lane = tid&31;
    const int wm = (wid&3)*32, wn = (wid>>2)*64;
    const int lr = lane>>2, lc = lane&3;

    for (int kt=0; kt<NT; kt++){
        const int buf = kt & 1;
        if (kt+1 < NT){
            load_tile(kt+1, buf^1);
            asm volatile("cp.async.wait_group 1;");
        } else {
            asm volatile("cp.async.wait_group 0;");
        }
        __syncthreads();
        // round-to-nearest tf32 conversion in place (RNA: unbiased)
        {
            float4* pa = reinterpret_cast<float4*>(&As[buf*TBUF]);
            float4* pb = reinterpret_cast<float4*>(&Bs[buf*TBUF]);
            #pragma unroll
            for (int i=0;i<5;i++){
                int idx = tid + i*256;
                if (idx < 1152){
                    float4 v = pa[idx];
                    v.x=to_tf32(v.x); v.y=to_tf32(v.y); v.z=to_tf32(v.z); v.w=to_tf32(v.w);
                    pa[idx]=v;
                    v = pb[idx];
                    v.x=to_tf32(v.x); v.y=to_tf32(v.y); v.z=to_tf32(v.z); v.w=to_tf32(v.w);
                    pb[idx]=v;
                }
            }
        }
        __syncthreads();
        const float* As_ = &As[buf*TBUF];
        const float* Bs_ = &Bs[buf*TBUF];
        #pragma unroll
        for (int kk=0; kk<4; kk++){
            uint32_t a[2][4], b[8][2];
            const int c = kk*8 + lc;
            #pragma unroll
            for (int mi=0; mi<2; mi++){
                int r = wm + mi*16 + lr;
                a[mi][0] = fbits(As_[r*SMA + c]);
                a[mi][1] = fbits(As_[(r+8)*SMA + c]);
                a[mi][2] = fbits(As_[r*SMA + c + 4]);
                a[mi][3] = fbits(As_[(r+8)*SMA + c + 4]);
            }
            #pragma unroll
            for (int ni=0; ni<8; ni++){
                int n = wn + ni*8 + lr;
                b[ni][0] = fbits(Bs_[n*SMA + c]);
                b[ni][1] = fbits(Bs_[n*SMA + c + 4]);
            }
            #pragma unroll
            for (int mi=0;mi<2;mi++)
                #pragma unroll
                for (int ni=0;ni<8;ni++)
                    mma8(acc[mi][ni], a[mi], b[ni]);
        }
        __syncthreads();
    }

    // ---------------- epilogue ----------------
    if constexpr (MODE == 0){
        const int sec = n0 / DIMC;  // 0=Q, 1=K, 2=V (128 | 768 so block stays in one section)
        #pragma unroll
        for (int mi=0; mi<2; mi++){
            #pragma unroll
            for (int rh=0; rh<2; rh++){
                int m = m0 + wm + mi*16 + rh*8 + lr;
                int bb = m / SEQ;
                int t  = m - bb*SEQ;
                #pragma unroll
                for (int ni=0; ni<8; ni++){
                    #pragma unroll
                    for (int cp=0; cp<2; cp++){
                        int n = n0 + wn + ni*8 + lc*2 + cp;
                        int d = n - sec*DIMC;
                        int h = d >> 6, hdc = d & 63;
                        float v = acc[mi][ni][rh*2 + cp];
                        int dst = ((bb*HEADS + h)*SEQ + t)*HD + hdc;
                        if (sec == 0)      g_Q[dst] = (v + bias_a[d]) * QSCALE;
                        else if (sec == 1) g_K[dst] = v;
                        else               g_V[dst] = v + bias_b[d];
                    }
                }
            }
        }
    } else {
        #pragma unroll
        for (int mi=0; mi<2; mi++){
            #pragma unroll
            for (int rh=0; rh<2; rh++){
                int m = m0 + wm + mi*16 + rh*8 + lr;
                #pragma unroll
                for (int ni=0; ni<8; ni++){
                    #pragma unroll
                    for (int cp=0; cp<2; cp++){
                        int n = n0 + wn + ni*8 + lc*2 + cp;
                        Out[(size_t)m*DIMC + n] = acc[mi][ni][rh*2 + cp] + bias_a[n];
                    }
                }
            }
        }
    }
}

// ---------------- attention: one block per (b, h, 64-row q-tile) ----------------
// S = Q K^T + bias (keys padded 197->208); softmax; O = P V
#define NK 208               /* padded key count (13 * 16) */
#define LQ 68                /* Q/K/V smem row stride */
#define LP 212               /* P smem row stride */
__global__ void __launch_bounds__(256) attn_kernel(){
    extern __shared__ float sm[];
    float* Qs = sm;                   // 64  * 68
    float* Ks = Qs + 64*LQ;           // 208 * 68
    float* Vs = Ks + NK*LQ;           // 208 * 68
    float* Ps = Vs + NK*LQ;           // 64  * 212

    const int tid = threadIdx.x;
    const int qt = blockIdx.x, h = blockIdx.y, b = blockIdx.z;
    const size_t base = (size_t)(b*HEADS + h)*SEQ*HD;

    // load Q tile (tf32-rounded; pad rows zero)
    #pragma unroll
    for (int i=0;i<4;i++){
        int idx = tid + i*256;                 // 0..1023
        int row = idx >> 4, c4 = (idx & 15)*4;
        int q = qt*64 + row;
        float4 v = make_float4(0.f,0.f,0.f,0.f);
        if (q < SEQ) v = *reinterpret_cast<const float4*>(&g_Q[base + (size_t)q*HD + c4]);
        v.x=to_tf32(v.x); v.y=to_tf32(v.y); v.z=to_tf32(v.z); v.w=to_tf32(v.w);
        *reinterpret_cast<float4*>(&Qs[row*LQ + c4]) = v;
    }
    // load K and V (208 rows, zero-padded past 197)
    #pragma unroll
    for (int i=0;i<13;i++){
        int idx = tid + i*256;                 // 0..3327
        int row = idx >> 4, c4 = (idx & 15)*4;
        float4 v = make_float4(0.f,0.f,0.f,0.f);
        if (row < SEQ) v = *reinterpret_cast<const float4*>(&g_K[base + (size_t)row*HD + c4]);
        v.x=to_tf32(v.x); v.y=to_tf32(v.y); v.z=to_tf32(v.z); v.w=to_tf32(v.w);
        *reinterpret_cast<float4*>(&Ks[row*LQ + c4]) = v;
        v = make_float4(0.f,0.f,0.f,0.f);
        if (row < SEQ) v = *reinterpret_cast<const float4*>(&g_V[base + (size_t)row*HD + c4]);
        v.x=to_tf32(v.x); v.y=to_tf32(v.y); v.z=to_tf32(v.z); v.w=to_tf32(v.w);
        *reinterpret_cast<float4*>(&Vs[row*LQ + c4]) = v;
    }
    __syncthreads();

    const int wid = tid>>5, lane = tid&31, lr = lane>>2, lc = lane&3;

    // -------- phase 1: S = Q K^T, 8 warps as 4(m) x 2(n), warp tile 16 x 104 --------
    {
        const int wm = (wid&3)*16, wn = (wid>>2)*104;
        float acc[13][4];
        #pragma unroll
        for (int ni=0;ni<13;ni++)
            #pragma unroll
            for (int r=0;r<4;r++) acc[ni][r]=0.f;
        #pragma unroll
        for (int kk=0; kk<8; kk++){
            const int c = kk*8 + lc;
            uint32_t a[4];
            int r = wm + lr;
            a[0]=fbits(Qs[r*LQ+c]); a[1]=fbits(Qs[(r+8)*LQ+c]);
            a[2]=fbits(Qs[r*LQ+c+4]); a[3]=fbits(Qs[(r+8)*LQ+c+4]);
            #pragma unroll
            for (int ni=0; ni<13; ni++){
                uint32_t bf[2];
                int n = wn + ni*8 + lr;
                bf[0]=fbits(Ks[n*LQ+c]); bf[1]=fbits(Ks[n*LQ+c+4]);
                mma8(acc[ni], a, bf);
            }
        }
        // S + rel-pos bias -> Ps (masked cols = -1e30)
        #pragma unroll
        for (int ni=0; ni<13; ni++){
            #pragma unroll
            for (int r=0;r<4;r++){
                int row = wm + (r>>1)*8 + lr;
                int j   = wn + ni*8 + lc*2 + (r&1);
                int qg  = qt*64 + row;
                float v;
                if (j >= SEQ) v = -1e30f;
                else if (qg < SEQ) v = acc[ni][r] + g_BIAS[(h*SEQ + qg)*SEQ + j];
                else v = 0.f;
                Ps[row*LP + j] = v;
            }
        }
    }
    __syncthreads();

    // -------- softmax (warp w handles rows w, w+8, ..., w+56) --------
    #pragma unroll
    for (int rr=0; rr<8; rr++){
        int row = (tid>>5) + rr*8;
        float* prow = &Ps[row*LP];
        float vals[7];
        float mx = -1e30f;
        #pragma unroll
        for (int i=0;i<7;i++){
            int j = lane + i*32;
            vals[i] = (j < NK) ? prow[j] : -1e30f;
            mx = fmaxf(mx, vals[i]);
        }
        #pragma unroll
        for (int o=16;o>0;o>>=1) mx = fmaxf(mx, __shfl_xor_sync(0xffffffffu, mx, o));
        float s = 0.f;
        #pragma unroll
        for (int i=0;i<7;i++){ vals[i] = __expf(vals[i]-mx); s += vals[i]; }
        #pragma unroll
        for (int o=16;o>0;o>>=1) s += __shfl_xor_sync(0xffffffffu, s, o);
        float inv = 1.f / s;
        #pragma unroll
        for (int i=0;i<7;i++){
            int j = lane + i*32;
            if (j < NK) prow[j] = to_tf32(vals[i]*inv);
        }
    }
    __syncthreads();

    // -------- phase 2: O = P V, warp tile 16 x 32, K = 208 --------
    {
        const int wm = (wid&3)*16, wn = (wid>>2)*32;
        float acc[4][4];
        #pragma unroll
        for (int ni=0;ni<4;ni++)
            #pragma unroll
            for (int r=0;r<4;r++) acc[ni][r]=0.f;
        #pragma unroll
        for (int ks=0; ks<26; ks++){
            const int c = ks*8 + lc;
            uint32_t a[4];
            int r = wm + lr;
            a[0]=fbits(Ps[r*LP+c]); a[1]=fbits(Ps[(r+8)*LP+c]);
            a[2]=fbits(Ps[r*LP+c+4]); a[3]=fbits(Ps[(r+8)*LP+c+4]);
            #pragma unroll
            for (int ni=0;ni<4;ni++){
                uint32_t bf[2];
                int n = wn + ni*8 + lr;
                bf[0]=fbits(Vs[c*LQ + n]);
                bf[1]=fbits(Vs[(c+4)*LQ + n]);
                mma8(acc[ni], a, bf);
            }
        }
        #pragma unroll
        for (int ni=0;ni<4;ni++){
            #pragma unroll
            for (int r=0;r<4;r++){
                int row = wm + (r>>1)*8 + lr;
                int hdc = wn + ni*8 + lc*2 + (r&1);
                int qg  = qt*64 + row;
                if (qg < SEQ)
                    g_ATT[((size_t)b*SEQ + qg)*DIMC + h*HD + hdc] = acc[ni][r];
            }
        }
    }
}

// ---------------- launch ----------------
extern "C" void kernel_launch(void* const* d_in, const int* in_sizes, int n_in,
                              void* d_out, int out_size){
    const float* x      = (const float*)d_in[0];
    const float* qkv_w  = (const float*)d_in[1];
    const float* q_bias = (const float*)d_in[2];
    const float* v_bias = (const float*)d_in[3];
    const float* table  = (const float*)d_in[4];
    const float* proj_w = (const float*)d_in[5];
    const float* proj_b = (const float*)d_in[6];
    const int*   relidx = (const int*)d_in[7];
    float* out = (float*)d_out;

    const int gemm_smem = 4 * TBUF * (int)sizeof(float);              // 73728
    const int attn_smem = (64*LQ + 2*NK*LQ + 64*LP) * (int)sizeof(float); // 184832
    cudaFuncSetAttribute(gemm_tf32<0>, cudaFuncAttributeMaxDynamicSharedMemorySize, gemm_smem);
    cudaFuncSetAttribute(gemm_tf32<1>, cudaFuncAttributeMaxDynamicSharedMemorySize, gemm_smem);
    cudaFuncSetAttribute(attn_kernel,  cudaFuncAttributeMaxDynamicSharedMemorySize, attn_smem);

    bias_gather_kernel<<<(HEADS*SEQ*SEQ + 255)/256, 256>>>(table, relidx);

    gemm_tf32<0><<<dim3(3*DIMC/128, MTOT/128), 256, gemm_smem>>>(
        x, qkv_w, q_bias, v_bias, nullptr);

    attn_kernel<<<dim3((SEQ + 63)/64, HEADS, BATCH), 256, attn_smem>>>();

    gemm_tf32<1><<<dim3(DIMC/128, MTOT/128), 256, gemm_smem>>>(
        nullptr, proj_w, proj_b, nullptr, out);
}

// round 12
// speedup vs baseline: 1.0005x; 1.0005x over previous
#include <cuda_runtime.h>
#include <cstdint>

#define BATCH 256
#define SEQ   197
#define DIMC  768
#define HEADS 12
#define HD    64
#define NRD   732
#define MTOT  (BATCH*SEQ)      /* 50432 */
#define QSCALE 0.125f          /* 64^-0.5 */

// ---------------- scratch (static device globals; no allocation) ----------------
__device__ __align__(16) float g_Q[BATCH*HEADS*SEQ*HD];
__device__ __align__(16) float g_K[BATCH*HEADS*SEQ*HD];
__device__ __align__(16) float g_V[BATCH*HEADS*SEQ*HD];
__device__ __align__(16) float g_ATT[(size_t)MTOT*DIMC];
__device__ __align__(16) float g_BIAS[HEADS*SEQ*SEQ];

// ---------------- helpers ----------------
__device__ __forceinline__ float to_tf32(float x){
    float r; asm("cvt.rna.tf32.f32 %0, %1;" : "=f"(r) : "f"(x)); return r;
}
__device__ __forceinline__ void cp16(void* s, const void* g){
    unsigned saddr = (unsigned)__cvta_generic_to_shared(s);
    asm volatile("cp.async.cg.shared.global [%0], [%1], 16;\n" :: "r"(saddr), "l"(g));
}
__device__ __forceinline__ void mma8(float* c, const uint32_t* a, const uint32_t* b){
    asm volatile("mma.sync.aligned.m16n8k8.row.col.f32.tf32.tf32.f32 "
        "{%0,%1,%2,%3}, {%4,%5,%6,%7}, {%8,%9}, {%0,%1,%2,%3};"
        : "+f"(c[0]),"+f"(c[1]),"+f"(c[2]),"+f"(c[3])
        : "r"(a[0]),"r"(a[1]),"r"(a[2]),"r"(a[3]),"r"(b[0]),"r"(b[1]));
}
__device__ __forceinline__ uint32_t fbits(float x){ return __float_as_uint(x); }

// ---------------- bias gather: g_BIAS[h][i][j] = table[rel_index[i][j]][h] ----------------
__global__ void bias_gather_kernel(const float* __restrict__ table,
                                   const int* __restrict__ rel_index){
    int idx = blockIdx.x * 256 + threadIdx.x;
    const int tot = HEADS*SEQ*SEQ;
    if (idx >= tot) return;
    int h  = idx / (SEQ*SEQ);
    int ij = idx - h*(SEQ*SEQ);
    g_BIAS[idx] = table[rel_index[ij]*HEADS + h];
}

// ---------------- TF32 GEMM 128x128x32, C[m,n] = sum_k A[m,k]*W[n,k] ----------------
// MODE 0: A = x param, epilogue -> Q (scale+q_bias), K, V  (n spans 2304)
// MODE 1: A = g_ATT,   epilogue -> out + proj_b            (n spans 768)
#define SMA 36              /* smem row stride (floats), padded vs 32 */
#define TBUF 4608           /* 128*36 floats per buffer */
template<int MODE>
__global__ void __launch_bounds__(256,2) gemm_tf32(
    const float* __restrict__ A, const float* __restrict__ W,
    const float* __restrict__ bias_a, const float* __restrict__ bias_b,
    float* __restrict__ Out)
{
    const int K = DIMC;
    extern __shared__ float sm[];
    float* As = sm;             // 2 * TBUF
    float* Bs = sm + 2*TBUF;    // 2 * TBUF
    const int tid = threadIdx.x;
    const int m0 = blockIdx.y * 128;
    const int n0 = blockIdx.x * 128;
    const float* Ap = (MODE == 0) ? A : g_ATT;

    float acc[2][8][4];
    #pragma unroll
    for (int i=0;i<2;i++)
        #pragma unroll
        for (int j=0;j<8;j++)
            #pragma unroll
            for (int r=0;r<4;r++) acc[i][j][r]=0.f;

    const int NT = K/32;  // 24
    auto load_tile = [&](int kt, int buf){
        const int k0 = kt*32;
        #pragma unroll
        for (int i=0;i<4;i++){
            int idx = tid + i*256;               // 0..1023
            int row = idx >> 3, c4 = (idx & 7)*4;
            cp16(&As[buf*TBUF + row*SMA + c4], &Ap[(size_t)(m0+row)*K + k0 + c4]);
        }
        #pragma unroll
        for (int i=0;i<4;i++){
            int idx = tid + i*256;
            int row = idx >> 3, c4 = (idx & 7)*4;
            cp16(&Bs[buf*TBUF + row*SMA + c4], &W[(size_t)(n0+row)*K + k0 + c4]);
        }
        asm volatile("cp.async.commit_group;");
    };
    load_tile(0, 0);

    const int wid = tid>>5, lane = tid&31;
    const int wm = (wid&3)*32, wn = (wid>>2)*64;
    const int lr = lane>>2, lc = lane&3;

    for (int kt=0; kt<NT; kt++){
        const int buf = kt & 1;
        if (kt+1 < NT){
            load_tile(kt+1, buf^1);
            asm volatile("cp.async.wait_group 1;");
        } else {
            asm volatile("cp.async.wait_group 0;");
        }
        __syncthreads();
        // round-to-nearest tf32 conversion in place (RNA: unbiased)
        {
            float4* pa = reinterpret_cast<float4*>(&As[buf*TBUF]);
            float4* pb = reinterpret_cast<float4*>(&Bs[buf*TBUF]);
            #pragma unroll
            for (int i=0;i<5;i++){
                int idx = tid + i*256;
                if (idx < 1152){
                    float4 v = pa[idx];
                    v.x=to_tf32(v.x); v.y=to_tf32(v.y); v.z=to_tf32(v.z); v.w=to_tf32(v.w);
                    pa[idx]=v;
                    v = pb[idx];
                    v.x=to_tf32(v.x); v.y=to_tf32(v.y); v.z=to_tf32(v.z); v.w=to_tf32(v.w);
                    pb[idx]=v;
                }
            }
        }
        __syncthreads();
        const float* As_ = &As[buf*TBUF];
        const float* Bs_ = &Bs[buf*TBUF];
        #pragma unroll
        for (int kk=0; kk<4; kk++){
            uint32_t a[2][4], b[8][2];
            const int c = kk*8 + lc;
            #pragma unroll
            for (int mi=0; mi<2; mi++){
                int r = wm + mi*16 + lr;
                a[mi][0] = fbits(As_[r*SMA + c]);
                a[mi][1] = fbits(As_[(r+8)*SMA + c]);
                a[mi][2] = fbits(As_[r*SMA + c + 4]);
                a[mi][3] = fbits(As_[(r+8)*SMA + c + 4]);
            }
            #pragma unroll
            for (int ni=0; ni<8; ni++){
                int n = wn + ni*8 + lr;
                b[ni][0] = fbits(Bs_[n*SMA + c]);
                b[ni][1] = fbits(Bs_[n*SMA + c + 4]);
            }
            #pragma unroll
            for (int mi=0;mi<2;mi++)
                #pragma unroll
                for (int ni=0;ni<8;ni++)
                    mma8(acc[mi][ni], a[mi], b[ni]);
        }
        __syncthreads();
    }

    // ---------------- epilogue ----------------
    if constexpr (MODE == 0){
        const int sec = n0 / DIMC;  // 0=Q, 1=K, 2=V (128 | 768 so block stays in one section)
        #pragma unroll
        for (int mi=0; mi<2; mi++){
            #pragma unroll
            for (int rh=0; rh<2; rh++){
                int m = m0 + wm + mi*16 + rh*8 + lr;
                int bb = m / SEQ;
                int t  = m - bb*SEQ;
                #pragma unroll
                for (int ni=0; ni<8; ni++){
                    #pragma unroll
                    for (int cp=0; cp<2; cp++){
                        int n = n0 + wn + ni*8 + lc*2 + cp;
                        int d = n - sec*DIMC;
                        int h = d >> 6, hdc = d & 63;
                        float v = acc[mi][ni][rh*2 + cp];
                        int dst = ((bb*HEADS + h)*SEQ + t)*HD + hdc;
                        if (sec == 0)      g_Q[dst] = (v + bias_a[d]) * QSCALE;
                        else if (sec == 1) g_K[dst] = v;
                        else               g_V[dst] = v + bias_b[d];
                    }
                }
            }
        }
    } else {
        #pragma unroll
        for (int mi=0; mi<2; mi++){
            #pragma unroll
            for (int rh=0; rh<2; rh++){
                int m = m0 + wm + mi*16 + rh*8 + lr;
                #pragma unroll
                for (int ni=0; ni<8; ni++){
                    #pragma unroll
                    for (int cp=0; cp<2; cp++){
                        int n = n0 + wn + ni*8 + lc*2 + cp;
                        Out[(size_t)m*DIMC + n] = acc[mi][ni][rh*2 + cp] + bias_a[n];
                    }
                }
            }
        }
    }
}

// ---------------- attention: one block per (b, h, 64-row q-tile) ----------------
// S = Q K^T + bias (keys padded 197->208); softmax; O = P V
#define NK 208               /* padded key count (13 * 16) */
#define LQ 68                /* Q/K/V smem row stride */
#define LP 212               /* P smem row stride */
__global__ void __launch_bounds__(256) attn_kernel(){
    extern __shared__ float sm[];
    float* Qs = sm;                   // 64  * 68
    float* Ks = Qs + 64*LQ;           // 208 * 68
    float* Vs = Ks + NK*LQ;           // 208 * 68
    float* Ps = Vs + NK*LQ;           // 64  * 212

    const int tid = threadIdx.x;
    const int qt = blockIdx.x, h = blockIdx.y, b = blockIdx.z;
    const size_t base = (size_t)(b*HEADS + h)*SEQ*HD;

    // load Q tile (tf32-rounded; pad rows zero)
    #pragma unroll
    for (int i=0;i<4;i++){
        int idx = tid + i*256;                 // 0..1023
        int row = idx >> 4, c4 = (idx & 15)*4;
        int q = qt*64 + row;
        float4 v = make_float4(0.f,0.f,0.f,0.f);
        if (q < SEQ) v = *reinterpret_cast<const float4*>(&g_Q[base + (size_t)q*HD + c4]);
        v.x=to_tf32(v.x); v.y=to_tf32(v.y); v.z=to_tf32(v.z); v.w=to_tf32(v.w);
        *reinterpret_cast<float4*>(&Qs[row*LQ + c4]) = v;
    }
    // load K and V (208 rows, zero-padded past 197)
    #pragma unroll
    for (int i=0;i<13;i++){
        int idx = tid + i*256;                 // 0..3327
        int row = idx >> 4, c4 = (idx & 15)*4;
        float4 v = make_float4(0.f,0.f,0.f,0.f);
        if (row < SEQ) v = *reinterpret_cast<const float4*>(&g_K[base + (size_t)row*HD + c4]);
        v.x=to_tf32(v.x); v.y=to_tf32(v.y); v.z=to_tf32(v.z); v.w=to_tf32(v.w);
        *reinterpret_cast<float4*>(&Ks[row*LQ + c4]) = v;
        v = make_float4(0.f,0.f,0.f,0.f);
        if (row < SEQ) v = *reinterpret_cast<const float4*>(&g_V[base + (size_t)row*HD + c4]);
        v.x=to_tf32(v.x); v.y=to_tf32(v.y); v.z=to_tf32(v.z); v.w=to_tf32(v.w);
        *reinterpret_cast<float4*>(&Vs[row*LQ + c4]) = v;
    }
    __syncthreads();

    const int wid = tid>>5, lane = tid&31, lr = lane>>2, lc = lane&3;

    // -------- phase 1: S = Q K^T, 8 warps as 4(m) x 2(n), warp tile 16 x 104 --------
    {
        const int wm = (wid&3)*16, wn = (wid>>2)*104;
        float acc[13][4];
        #pragma unroll
        for (int ni=0;ni<13;ni++)
            #pragma unroll
            for (int r=0;r<4;r++) acc[ni][r]=0.f;
        #pragma unroll
        for (int kk=0; kk<8; kk++){
            const int c = kk*8 + lc;
            uint32_t a[4];
            int r = wm + lr;
            a[0]=fbits(Qs[r*LQ+c]); a[1]=fbits(Qs[(r+8)*LQ+c]);
            a[2]=fbits(Qs[r*LQ+c+4]); a[3]=fbits(Qs[(r+8)*LQ+c+4]);
            #pragma unroll
            for (int ni=0; ni<13; ni++){
                uint32_t bf[2];
                int n = wn + ni*8 + lr;
                bf[0]=fbits(Ks[n*LQ+c]); bf[1]=fbits(Ks[n*LQ+c+4]);
                mma8(acc[ni], a, bf);
            }
        }
        // S + rel-pos bias -> Ps (masked cols = -1e30)
        #pragma unroll
        for (int ni=0; ni<13; ni++){
            #pragma unroll
            for (int r=0;r<4;r++){
                int row = wm + (r>>1)*8 + lr;
                int j   = wn + ni*8 + lc*2 + (r&1);
                int qg  = qt*64 + row;
                float v;
                if (j >= SEQ) v = -1e30f;
                else if (qg < SEQ) v = acc[ni][r] + g_BIAS[(h*SEQ + qg)*SEQ + j];
                else v = 0.f;
                Ps[row*LP + j] = v;
            }
        }
    }
    __syncthreads();

    // -------- softmax (warp w handles rows w, w+8, ..., w+56) --------
    #pragma unroll
    for (int rr=0; rr<8; rr++){
        int row = (tid>>5) + rr*8;
        float* prow = &Ps[row*LP];
        float vals[7];
        float mx = -1e30f;
        #pragma unroll
        for (int i=0;i<7;i++){
            int j = lane + i*32;
            vals[i] = (j < NK) ? prow[j] : -1e30f;
            mx = fmaxf(mx, vals[i]);
        }
        #pragma unroll
        for (int o=16;o>0;o>>=1) mx = fmaxf(mx, __shfl_xor_sync(0xffffffffu, mx, o));
        float s = 0.f;
        #pragma unroll
        for (int i=0;i<7;i++){ vals[i] = __expf(vals[i]-mx); s += vals[i]; }
        #pragma unroll
        for (int o=16;o>0;o>>=1) s += __shfl_xor_sync(0xffffffffu, s, o);
        float inv = 1.f / s;
        #pragma unroll
        for (int i=0;i<7;i++){
            int j = lane + i*32;
            if (j < NK) prow[j] = to_tf32(vals[i]*inv);
        }
    }
    __syncthreads();

    // -------- phase 2: O = P V, warp tile 16 x 32, K = 208 --------
    {
        const int wm = (wid&3)*16, wn = (wid>>2)*32;
        float acc[4][4];
        #pragma unroll
        for (int ni=0;ni<4;ni++)
            #pragma unroll
            for (int r=0;r<4;r++) acc[ni][r]=0.f;
        #pragma unroll
        for (int ks=0; ks<26; ks++){
            const int c = ks*8 + lc;
            uint32_t a[4];
            int r = wm + lr;
            a[0]=fbits(Ps[r*LP+c]); a[1]=fbits(Ps[(r+8)*LP+c]);
            a[2]=fbits(Ps[r*LP+c+4]); a[3]=fbits(Ps[(r+8)*LP+c+4]);
            #pragma unroll
            for (int ni=0;ni<4;ni++){
                uint32_t bf[2];
                int n = wn + ni*8 + lr;
                bf[0]=fbits(Vs[c*LQ + n]);
                bf[1]=fbits(Vs[(c+4)*LQ + n]);
                mma8(acc[ni], a, bf);
            }
        }
        #pragma unroll
        for (int ni=0;ni<4;ni++){
            #pragma unroll
            for (int r=0;r<4;r++){
                int row = wm + (r>>1)*8 + lr;
                int hdc = wn + ni*8 + lc*2 + (r&1);
                int qg  = qt*64 + row;
                if (qg < SEQ)
                    g_ATT[((size_t)b*SEQ + qg)*DIMC + h*HD + hdc] = acc[ni][r];
            }
        }
    }
}

// ---------------- launch ----------------
extern "C" void kernel_launch(void* const* d_in, const int* in_sizes, int n_in,
                              void* d_out, int out_size){
    const float* x      = (const float*)d_in[0];
    const float* qkv_w  = (const float*)d_in[1];
    const float* q_bias = (const float*)d_in[2];
    const float* v_bias = (const float*)d_in[3];
    const float* table  = (const float*)d_in[4];
    const float* proj_w = (const float*)d_in[5];
    const float* proj_b = (const float*)d_in[6];
    const int*   relidx = (const int*)d_in[7];
    float* out = (float*)d_out;

    const int gemm_smem = 4 * TBUF * (int)sizeof(float);              // 73728
    const int attn_smem = (64*LQ + 2*NK*LQ + 64*LP) * (int)sizeof(float); // 184832
    cudaFuncSetAttribute(gemm_tf32<0>, cudaFuncAttributeMaxDynamicSharedMemorySize, gemm_smem);
    cudaFuncSetAttribute(gemm_tf32<1>, cudaFuncAttributeMaxDynamicSharedMemorySize, gemm_smem);
    cudaFuncSetAttribute(attn_kernel,  cudaFuncAttributeMaxDynamicSharedMemorySize, attn_smem);

    bias_gather_kernel<<<(HEADS*SEQ*SEQ + 255)/256, 256>>>(table, relidx);

    gemm_tf32<0><<<dim3(3*DIMC/128, MTOT/128), 256, gemm_smem>>>(
        x, qkv_w, q_bias, v_bias, nullptr);

    attn_kernel<<<dim3((SEQ + 63)/64, HEADS, BATCH), 256, attn_smem>>>();

    gemm_tf32<1><<<dim3(DIMC/128, MTOT/128), 256, gemm_smem>>>(
        nullptr, proj_w, proj_b, nullptr, out);
}

// round 13
// speedup vs baseline: 1.2146x; 1.2140x over previous
#include <cuda_runtime.h>
#include <cstdint>

#define BATCH 256
#define SEQ   197
#define DIMC  768
#define HEADS 12
#define HD    64
#define MTOT  (BATCH*SEQ)      /* 50432 */
#define QSCALE 0.125f

// ---------------- scratch (static device globals; no allocation) ----------------
__device__ __align__(16) float g_X [(size_t)MTOT*DIMC];        // tf32-rounded x
__device__ __align__(16) float g_W1[3*DIMC*DIMC];              // tf32-rounded qkv_w
__device__ __align__(16) float g_W2[DIMC*DIMC];                // tf32-rounded proj_w
__device__ __align__(16) float g_Q[BATCH*HEADS*SEQ*HD];
__device__ __align__(16) float g_K[BATCH*HEADS*SEQ*HD];
__device__ __align__(16) float g_V[BATCH*HEADS*SEQ*HD];
__device__ __align__(16) float g_ATT[(size_t)MTOT*DIMC];
__device__ __align__(16) float g_BIAS[HEADS*SEQ*SEQ];

// ---------------- helpers ----------------
__device__ __forceinline__ float to_tf32(float x){
    float r; asm("cvt.rna.tf32.f32 %0, %1;" : "=f"(r) : "f"(x)); return r;
}
__device__ __forceinline__ void cp16(void* s, const void* g){
    unsigned saddr = (unsigned)__cvta_generic_to_shared(s);
    asm volatile("cp.async.cg.shared.global [%0], [%1], 16;\n" :: "r"(saddr), "l"(g));
}
__device__ __forceinline__ void mma8(float* c, const uint32_t* a, const uint32_t* b){
    asm volatile("mma.sync.aligned.m16n8k8.row.col.f32.tf32.tf32.f32 "
        "{%0,%1,%2,%3}, {%4,%5,%6,%7}, {%8,%9}, {%0,%1,%2,%3};"
        : "+f"(c[0]),"+f"(c[1]),"+f"(c[2]),"+f"(c[3])
        : "r"(a[0]),"r"(a[1]),"r"(a[2]),"r"(a[3]),"r"(b[0]),"r"(b[1]));
}
__device__ __forceinline__ uint32_t fbits(float x){ return __float_as_uint(x); }

// ---------------- prep: round to tf32 once (float4 elementwise) ----------------
template<int DST>
__global__ void round_tf32_kernel(const float* __restrict__ src, int n4){
    int i = blockIdx.x*256 + threadIdx.x;
    if (i >= n4) return;
    float4 v = reinterpret_cast<const float4*>(src)[i];
    v.x=to_tf32(v.x); v.y=to_tf32(v.y); v.z=to_tf32(v.z); v.w=to_tf32(v.w);
    float* dst = (DST==0) ? g_X : (DST==1) ? g_W1 : g_W2;
    reinterpret_cast<float4*>(dst)[i] = v;
}

// ---------------- bias gather: g_BIAS[h][i][j] = table[rel_index[i][j]][h] ----------------
__global__ void bias_gather_kernel(const float* __restrict__ table,
                                   const int* __restrict__ rel_index){
    int idx = blockIdx.x * 256 + threadIdx.x;
    const int tot = HEADS*SEQ*SEQ;
    if (idx >= tot) return;
    int h  = idx / (SEQ*SEQ);
    int ij = idx - h*(SEQ*SEQ);
    g_BIAS[idx] = table[rel_index[ij]*HEADS + h];
}

// ---------------- TF32 GEMM 128x128x32 (operands pre-rounded) ----------------
// MODE 0: A=g_X,   W=g_W1, epilogue -> g_Q (scale+q_bias, rounded), g_K, g_V (rounded)
// MODE 1: A=g_ATT, W=g_W2, epilogue -> Out + proj_b (raw fp32)
#define SMA 36
#define TBUF 4608           /* 128*36 floats per buffer */
template<int MODE>
__global__ void __launch_bounds__(256,2) gemm_tf32(
    const float* __restrict__ bias_a, const float* __restrict__ bias_b,
    float* __restrict__ Out)
{
    const int K = DIMC;
    extern __shared__ float sm[];
    float* As = sm;             // 2 * TBUF
    float* Bs = sm + 2*TBUF;    // 2 * TBUF
    const int tid = threadIdx.x;
    const int m0 = blockIdx.y * 128;
    const int n0 = blockIdx.x * 128;
    const float* Ap = (MODE == 0) ? g_X  : g_ATT;
    const float* Wp = (MODE == 0) ? g_W1 : g_W2;

    float acc[2][8][4];
    #pragma unroll
    for (int i=0;i<2;i++)
        #pragma unroll
        for (int j=0;j<8;j++)
            #pragma unroll
            for (int r=0;r<4;r++) acc[i][j][r]=0.f;

    const int NT = K/32;  // 24
    auto load_tile = [&](int kt, int buf){
        const int k0 = kt*32;
        #pragma unroll
        for (int i=0;i<4;i++){
            int idx = tid + i*256;               // 0..1023
            int row = idx >> 3, c4 = (idx & 7)*4;
            cp16(&As[buf*TBUF + row*SMA + c4], &Ap[(size_t)(m0+row)*K + k0 + c4]);
        }
        #pragma unroll
        for (int i=0;i<4;i++){
            int idx = tid + i*256;
            int row = idx >> 3, c4 = (idx & 7)*4;
            cp16(&Bs[buf*TBUF + row*SMA + c4], &Wp[(size_t)(n0+row)*K + k0 + c4]);
        }
        asm volatile("cp.async.commit_group;");
    };
    load_tile(0, 0);

    const int wid = tid>>5, lane = tid&31;
    const int wm = (wid&3)*32, wn = (wid>>2)*64;
    const int lr = lane>>2, lc = lane&3;

    for (int kt=0; kt<NT; kt++){
        const int buf = kt & 1;
        asm volatile("cp.async.wait_group 0;");
        __syncthreads();                       // tile kt visible + prev reads of buf^1 done
        if (kt+1 < NT) load_tile(kt+1, buf^1); // overlaps with MMA below
        const float* As_ = &As[buf*TBUF];
        const float* Bs_ = &Bs[buf*TBUF];
        #pragma unroll
        for (int kk=0; kk<4; kk++){
            uint32_t a[2][4], b[8][2];
            const int c = kk*8 + lc;
            #pragma unroll
            for (int mi=0; mi<2; mi++){
                int r = wm + mi*16 + lr;
                a[mi][0] = fbits(As_[r*SMA + c]);
                a[mi][1] = fbits(As_[(r+8)*SMA + c]);
                a[mi][2] = fbits(As_[r*SMA + c + 4]);
                a[mi][3] = fbits(As_[(r+8)*SMA + c + 4]);
            }
            #pragma unroll
            for (int ni=0; ni<8; ni++){
                int n = wn + ni*8 + lr;
                b[ni][0] = fbits(Bs_[n*SMA + c]);
                b[ni][1] = fbits(Bs_[n*SMA + c + 4]);
            }
            #pragma unroll
            for (int mi=0;mi<2;mi++)
                #pragma unroll
                for (int ni=0;ni<8;ni++)
                    mma8(acc[mi][ni], a[mi], b[ni]);
        }
        __syncthreads();                       // all warps done with buf before it is refilled
    }

    // ---------------- epilogue ----------------
    if constexpr (MODE == 0){
        const int sec = n0 / DIMC;  // 0=Q, 1=K, 2=V (128 | 768: block stays in one section)
        #pragma unroll
        for (int mi=0; mi<2; mi++){
            #pragma unroll
            for (int rh=0; rh<2; rh++){
                int m = m0 + wm + mi*16 + rh*8 + lr;
                int bb = m / SEQ;
                int t  = m - bb*SEQ;
                #pragma unroll
                for (int ni=0; ni<8; ni++){
                    #pragma unroll
                    for (int cp=0; cp<2; cp++){
                        int n = n0 + wn + ni*8 + lc*2 + cp;
                        int d = n - sec*DIMC;
                        int h = d >> 6, hdc = d & 63;
                        float v = acc[mi][ni][rh*2 + cp];
                        int dst = ((bb*HEADS + h)*SEQ + t)*HD + hdc;
                        if (sec == 0)      g_Q[dst] = to_tf32((v + bias_a[d]) * QSCALE);
                        else if (sec == 1) g_K[dst] = to_tf32(v);
                        else               g_V[dst] = to_tf32(v + bias_b[d]);
                    }
                }
            }
        }
    } else {
        #pragma unroll
        for (int mi=0; mi<2; mi++){
            #pragma unroll
            for (int rh=0; rh<2; rh++){
                int m = m0 + wm + mi*16 + rh*8 + lr;
                #pragma unroll
                for (int ni=0; ni<8; ni++){
                    #pragma unroll
                    for (int cp=0; cp<2; cp++){
                        int n = n0 + wn + ni*8 + lc*2 + cp;
                        Out[(size_t)m*DIMC + n] = acc[mi][ni][rh*2 + cp] + bias_a[n];
                    }
                }
            }
        }
    }
}

// ---------------- attention: one block per (b, h); loops the 4 q-tiles ----------------
// K/V loaded into smem ONCE per (b,h); inputs are pre-rounded tf32 values.
#define NK 208               /* padded key count (13 * 16) */
#define LQ 68                /* Q/K/V smem row stride */
#define LP 212               /* P smem row stride */
__global__ void __launch_bounds__(256) attn_kernel(){
    extern __shared__ float sm[];
    float* Qs = sm;                   // 64  * 68
    float* Ks = Qs + 64*LQ;           // 208 * 68
    float* Vs = Ks + NK*LQ;           // 208 * 68
    float* Ps = Vs + NK*LQ;           // 64  * 212

    const int tid = threadIdx.x;
    const int h = blockIdx.x, b = blockIdx.y;
    const size_t base = (size_t)(b*HEADS + h)*SEQ*HD;

    // load K and V once (208 rows, zero-padded past 197) — values already tf32
    #pragma unroll
    for (int i=0;i<13;i++){
        int idx = tid + i*256;                 // 0..3327
        int row = idx >> 4, c4 = (idx & 15)*4;
        float4 v = make_float4(0.f,0.f,0.f,0.f);
        if (row < SEQ) v = *reinterpret_cast<const float4*>(&g_K[base + (size_t)row*HD + c4]);
        *reinterpret_cast<float4*>(&Ks[row*LQ + c4]) = v;
        v = make_float4(0.f,0.f,0.f,0.f);
        if (row < SEQ) v = *reinterpret_cast<const float4*>(&g_V[base + (size_t)row*HD + c4]);
        *reinterpret_cast<float4*>(&Vs[row*LQ + c4]) = v;
    }
    __syncthreads();

    const int wid = tid>>5, lane = tid&31, lr = lane>>2, lc = lane&3;

    for (int qt=0; qt<4; qt++){
        // load Q tile (pre-rounded; pad rows zero)
        #pragma unroll
        for (int i=0;i<4;i++){
            int idx = tid + i*256;             // 0..1023
            int row = idx >> 4, c4 = (idx & 15)*4;
            int q = qt*64 + row;
            float4 v = make_float4(0.f,0.f,0.f,0.f);
            if (q < SEQ) v = *reinterpret_cast<const float4*>(&g_Q[base + (size_t)q*HD + c4]);
            *reinterpret_cast<float4*>(&Qs[row*LQ + c4]) = v;
        }
        __syncthreads();

        // -------- phase 1: S = Q K^T, 8 warps as 4(m) x 2(n), warp tile 16 x 104 --------
        {
            const int wm = (wid&3)*16, wn = (wid>>2)*104;
            float acc[13][4];
            #pragma unroll
            for (int ni=0;ni<13;ni++)
                #pragma unroll
                for (int r=0;r<4;r++) acc[ni][r]=0.f;
            #pragma unroll
            for (int kk=0; kk<8; kk++){
                const int c = kk*8 + lc;
                uint32_t a[4];
                int r = wm + lr;
                a[0]=fbits(Qs[r*LQ+c]); a[1]=fbits(Qs[(r+8)*LQ+c]);
                a[2]=fbits(Qs[r*LQ+c+4]); a[3]=fbits(Qs[(r+8)*LQ+c+4]);
                #pragma unroll
                for (int ni=0; ni<13; ni++){
                    uint32_t bf[2];
                    int n = wn + ni*8 + lr;
                    bf[0]=fbits(Ks[n*LQ+c]); bf[1]=fbits(Ks[n*LQ+c+4]);
                    mma8(acc[ni], a, bf);
                }
            }
            // S + rel-pos bias -> Ps (masked cols = -1e30)
            #pragma unroll
            for (int ni=0; ni<13; ni++){
                #pragma unroll
                for (int r=0;r<4;r++){
                    int row = wm + (r>>1)*8 + lr;
                    int j   = wn + ni*8 + lc*2 + (r&1);
                    int qg  = qt*64 + row;
                    float v;
                    if (j >= SEQ) v = -1e30f;
                    else if (qg < SEQ) v = acc[ni][r] + g_BIAS[(h*SEQ + qg)*SEQ + j];
                    else v = 0.f;
                    Ps[row*LP + j] = v;
                }
            }
        }
        __syncthreads();

        // -------- softmax (warp w handles rows w, w+8, ..., w+56) --------
        #pragma unroll
        for (int rr=0; rr<8; rr++){
            int row = (tid>>5) + rr*8;
            float* prow = &Ps[row*LP];
            float vals[7];
            float mx = -1e30f;
            #pragma unroll
            for (int i=0;i<7;i++){
                int j = lane + i*32;
                vals[i] = (j < NK) ? prow[j] : -1e30f;
                mx = fmaxf(mx, vals[i]);
            }
            #pragma unroll
            for (int o=16;o>0;o>>=1) mx = fmaxf(mx, __shfl_xor_sync(0xffffffffu, mx, o));
            float s = 0.f;
            #pragma unroll
            for (int i=0;i<7;i++){ vals[i] = __expf(vals[i]-mx); s += vals[i]; }
            #pragma unroll
            for (int o=16;o>0;o>>=1) s += __shfl_xor_sync(0xffffffffu, s, o);
            float inv = 1.f / s;
            #pragma unroll
            for (int i=0;i<7;i++){
                int j = lane + i*32;
                if (j < NK) prow[j] = to_tf32(vals[i]*inv);
            }
        }
        __syncthreads();

        // -------- phase 2: O = P V, warp tile 16 x 32, K = 208 --------
        {
            const int wm = (wid&3)*16, wn = (wid>>2)*32;
            float acc[4][4];
            #pragma unroll
            for (int ni=0;ni<4;ni++)
                #pragma unroll
                for (int r=0;r<4;r++) acc[ni][r]=0.f;
            #pragma unroll
            for (int ks=0; ks<26; ks++){
                const int c = ks*8 + lc;
                uint32_t a[4];
                int r = wm + lr;
                a[0]=fbits(Ps[r*LP+c]); a[1]=fbits(Ps[(r+8)*LP+c]);
                a[2]=fbits(Ps[r*LP+c+4]); a[3]=fbits(Ps[(r+8)*LP+c+4]);
                #pragma unroll
                for (int ni=0;ni<4;ni++){
                    uint32_t bf[2];
                    int n = wn + ni*8 + lr;
                    bf[0]=fbits(Vs[c*LQ + n]);
                    bf[1]=fbits(Vs[(c+4)*LQ + n]);
                    mma8(acc[ni], a, bf);
                }
            }
            #pragma unroll
            for (int ni=0;ni<4;ni++){
                #pragma unroll
                for (int r=0;r<4;r++){
                    int row = wm + (r>>1)*8 + lr;
                    int hdc = wn + ni*8 + lc*2 + (r&1);
                    int qg  = qt*64 + row;
                    if (qg < SEQ)
                        g_ATT[((size_t)b*SEQ + qg)*DIMC + h*HD + hdc] = to_tf32(acc[ni][r]);
                }
            }
        }
        __syncthreads();   // before next q-tile overwrites Qs/Ps
    }
}

// ---------------- launch ----------------
extern "C" void kernel_launch(void* const* d_in, const int* in_sizes, int n_in,
                              void* d_out, int out_size){
    const float* x      = (const float*)d_in[0];
    const float* qkv_w  = (const float*)d_in[1];
    const float* q_bias = (const float*)d_in[2];
    const float* v_bias = (const float*)d_in[3];
    const float* table  = (const float*)d_in[4];
    const float* proj_w = (const float*)d_in[5];
    const float* proj_b = (const float*)d_in[6];
    const int*   relidx = (const int*)d_in[7];
    float* out = (float*)d_out;

    const int gemm_smem = 4 * TBUF * (int)sizeof(float);                    // 73728
    const int attn_smem = (64*LQ + 2*NK*LQ + 64*LP) * (int)sizeof(float);   // 184832
    cudaFuncSetAttribute(gemm_tf32<0>, cudaFuncAttributeMaxDynamicSharedMemorySize, gemm_smem);
    cudaFuncSetAttribute(gemm_tf32<1>, cudaFuncAttributeMaxDynamicSharedMemorySize, gemm_smem);
    cudaFuncSetAttribute(attn_kernel,  cudaFuncAttributeMaxDynamicSharedMemorySize, attn_smem);

    // prep: tf32-round inputs once
    const int nx4 = (MTOT*DIMC)/4;            // 9,682,944
    const int nw14 = (3*DIMC*DIMC)/4;         // 442,368
    const int nw24 = (DIMC*DIMC)/4;           // 147,456
    round_tf32_kernel<0><<<(nx4 +255)/256, 256>>>(x,      nx4);
    round_tf32_kernel<1><<<(nw14+255)/256, 256>>>(qkv_w,  nw14);
    round_tf32_kernel<2><<<(nw24+255)/256, 256>>>(proj_w, nw24);
    bias_gather_kernel<<<(HEADS*SEQ*SEQ + 255)/256, 256>>>(table, relidx);

    gemm_tf32<0><<<dim3(3*DIMC/128, MTOT/128), 256, gemm_smem>>>(
        q_bias, v_bias, nullptr);

    attn_kernel<<<dim3(HEADS, BATCH), 256, attn_smem>>>();

    gemm_tf32<1><<<dim3(DIMC/128, MTOT/128), 256, gemm_smem>>>(
        proj_b, nullptr, out);
}